// round 11
// baseline (speedup 1.0000x reference)
#include <cuda_runtime.h>
#include <cstdint>

// Problem constants
#define OUT_N 11008
#define IN_K  4096
#define GS    128
#define NG    32          // groups per row
#define M_TOK 8

// Tiling
#define BLOCK            256
#define WARPS            8
#define T_ROWS           4                      // output rows per warp
#define ROWS_PER_BLOCK   (WARPS * T_ROWS)       // 32 -> grid 344
#define SLOTS            4                      // smem stage slots (ring)
#define DEPTH            3                      // cp.async stages in flight

typedef unsigned long long u64;

// ---- packed f32x2 helpers (Blackwell FFMA2 path; ptxas won't emit from C++) ----
__device__ __forceinline__ u64 pkf(float lo, float hi) {
    u64 r; asm("mov.b64 %0, {%1, %2};" : "=l"(r) : "f"(lo), "f"(hi)); return r;
}
__device__ __forceinline__ u64 pki(unsigned lo, unsigned hi) {
    u64 r; asm("mov.b64 %0, {%1, %2};" : "=l"(r) : "r"(lo), "r"(hi)); return r;
}
__device__ __forceinline__ u64 add2(u64 a, u64 b) {
    u64 r; asm("add.rn.f32x2 %0, %1, %2;" : "=l"(r) : "l"(a), "l"(b)); return r;
}
__device__ __forceinline__ u64 mul2(u64 a, u64 b) {
    u64 r; asm("mul.rn.f32x2 %0, %1, %2;" : "=l"(r) : "l"(a), "l"(b)); return r;
}
__device__ __forceinline__ u64 fma2(u64 a, u64 b, u64 c) {
    u64 r; asm("fma.rn.f32x2 %0, %1, %2, %3;" : "=l"(r) : "l"(a), "l"(b), "l"(c)); return r;
}
__device__ __forceinline__ float2 upk(u64 a) {
    float lo, hi; asm("mov.b64 {%0, %1}, %2;" : "=f"(lo), "=f"(hi) : "l"(a));
    return make_float2(lo, hi);
}

// ---- cp.async (LDGSTS) helpers ----
__device__ __forceinline__ void cpa16(void* smem_ptr, const void* gptr) {
    const unsigned sa = (unsigned)__cvta_generic_to_shared(smem_ptr);
    asm volatile("cp.async.cg.shared.global [%0], [%1], 16;" :: "r"(sa), "l"(gptr));
}
__device__ __forceinline__ void cpa_commit() {
    asm volatile("cp.async.commit_group;");
}
__device__ __forceinline__ void cpa_wait() {
    asm volatile("cp.async.wait_group %0;" :: "n"(DEPTH - 1));
}

// One pipeline stage: weights for all 32 CTA rows of one group + x for that group.
struct Stage {
    int4   w[ROWS_PER_BLOCK][32];   // 16 KB : [row][lane]
    float4 xv[M_TOK][32];           //  4 KB : [token][lane]
};

// cp.async multistage pipeline; T_ROWS=4 amortizes the x smem reads (the R10
// L1tex wall) over 2x the weight bytes. Slot indices are compile-time.
__global__ void __launch_bounds__(BLOCK, 2)
qlinear_pergrp_kernel(const float* __restrict__ x,
                      const int*   __restrict__ qw,
                      const int*   __restrict__ qz,
                      const float* __restrict__ sc,
                      float*       __restrict__ out)
{
    __shared__ Stage st[SLOTS];                 // 80 KB

    const int tid  = threadIdx.x;
    const int warp = tid >> 5;
    const int lane = tid & 31;
    const int row_blk = blockIdx.x * ROWS_PER_BLOCK;
    const int row0 = row_blk + warp * T_ROWS;

    const float* scp = sc + (size_t)row0 * NG;  // 4 rows' [NG] tables
    const int*   qzp = qz + (size_t)row0 * NG;

    // ---- fill: 1280 16B chunks per stage, 5 per thread (4 weight + 1 x) ----
    auto fill = [&](int g, int slot) {
#pragma unroll
        for (int j = 0; j < 4; j++) {           // weight chunks 0..1023
            const int c = tid + j * 256;
            const int r = c >> 5, i = c & 31;
            cpa16(&st[slot].w[r][i],
                  qw + (size_t)(row_blk + r) * IN_K + g * GS + i * 4);
        }
        {                                        // x chunks 1024..1279
            const int m = tid >> 5, i = tid & 31;
            cpa16(&st[slot].xv[m][i],
                  x + (size_t)m * IN_K + g * GS + i * 4);
        }
    };

    // ---- prologue: stages 0..DEPTH-1 in flight ----
#pragma unroll
    for (int s = 0; s < DEPTH; s++) { fill(s, s); cpa_commit(); }

    u64 acc[T_ROWS][M_TOK];
#pragma unroll
    for (int r = 0; r < T_ROWS; r++)
#pragma unroll
        for (int m = 0; m < M_TOK; m++) acc[r][m] = 0ULL;

#pragma unroll 4
    for (int g = 0; g < NG; g++) {
        const int slot  = g & (SLOTS - 1);          // compile-time under unroll 4
        const int wslot = (g + DEPTH) & (SLOTS - 1);

        cpa_wait();                 // own chunks of stage g landed (DEPTH-1 pending)
        __syncthreads();            // everyone's chunks visible; also releases the
                                    // slot written below (read in iteration g-1)

        // per-group constants: warp-uniform L1-hit loads; dequant consts per row
        u64 ss[T_ROWS], zz[T_ROWS];
#pragma unroll
        for (int r = 0; r < T_ROWS; r++) {
            const float s = __ldg(scp + r * NG + g);
            const int   z = __ldg(qzp + r * NG + g);
            const float nz = __int_as_float((z | 0x4B000000) ^ 0x80000000);
            ss[r] = pkf(s, s);
            zz[r] = pkf(nz, nz);    // {-(z+2^23)} x2
        }

        // weights from smem ([row][lane] -> 512B contiguous, conflict-free),
        // dequant k-packed f32x2. as_float(q|0x4B000000)==2^23+q; +(-(2^23+z)) exact.
        u64 w01[T_ROWS], w23[T_ROWS];
#pragma unroll
        for (int r = 0; r < T_ROWS; r++) {
            const int4 q4 = st[slot].w[warp * T_ROWS + r][lane];
            w01[r] = mul2(add2(pki((unsigned)q4.x | 0x4B000000u,
                                   (unsigned)q4.y | 0x4B000000u), zz[r]), ss[r]);
            w23[r] = mul2(add2(pki((unsigned)q4.z | 0x4B000000u,
                                   (unsigned)q4.w | 0x4B000000u), zz[r]), ss[r]);
        }

#pragma unroll
        for (int m = 0; m < M_TOK; m++) {
            const float4 xv = st[slot].xv[m][lane];   // LDS.128, conflict-free
            const u64 x01 = pkf(xv.x, xv.y);          // adjacent regs -> free pair
            const u64 x23 = pkf(xv.z, xv.w);
#pragma unroll
            for (int r = 0; r < T_ROWS; r++) {
                acc[r][m] = fma2(w01[r], x01, acc[r][m]);
                acc[r][m] = fma2(w23[r], x23, acc[r][m]);
            }
        }

        // refill wslot = slot of iteration g-1; all its reads finished before the
        // __syncthreads above, so the overwrite is safe
        if (g + DEPTH < NG) fill(g + DEPTH, wslot);
        cpa_commit();               // (possibly empty) commit keeps wait counts aligned
    }

    // ---- fold f32x2 halves, then intra-warp reduction over the k-split ----
#pragma unroll
    for (int r = 0; r < T_ROWS; r++)
#pragma unroll
        for (int m = 0; m < M_TOK; m++) {
            const float2 v = upk(acc[r][m]);
            float s = v.x + v.y;
#pragma unroll
            for (int off = 16; off > 0; off >>= 1)
                s += __shfl_xor_sync(0xffffffffu, s, off);
            if (lane == 0)
                out[m * OUT_N + (row0 + r)] = s;
        }
}

extern "C" void kernel_launch(void* const* d_in, const int* in_sizes, int n_in,
                              void* d_out, int out_size)
{
    const float* x  = (const float*)d_in[0];   // [8, 4096] f32
    const int*   qw = (const int*)  d_in[1];   // [11008, 4096] int32 in [0,15]
    const int*   qz = (const int*)  d_in[2];   // [11008, 32] int32
    const float* sc = (const float*)d_in[3];   // [11008, 32] f32
    float* out = (float*)d_out;                // [8, 11008] f32

    const int grid = OUT_N / ROWS_PER_BLOCK;   // 344
    qlinear_pergrp_kernel<<<grid, BLOCK>>>(x, qw, qz, sc, out);
}